// round 16
// baseline (speedup 1.0000x reference)
#include <cuda_runtime.h>
#include <cuda_fp16.h>
#include <math.h>

#define NB 8192
#define BB 64
#define DD 5
#define NE (NB*DD)      // 40960 neighbor edges
#define NT (NB*BB)      // 524288 (node, batch) rows
#define HC 16

// ---------------- device scratch (no runtime allocation allowed) ------------
__device__ __half g_xlA[(size_t)NT * HC];   // 16.8 MB, layout (n,b,hc) fp16
__device__ __half g_xrA[(size_t)NT * HC];
__device__ __half g_xlB[(size_t)NT * HC];
__device__ __half g_xrB[(size_t)NT * HC];
__device__ __half g_h  [(size_t)NT * HC];   // final-layer h (fp16)
__device__ float  g_poolp[8 * BB * HC];     // pool partials (chunk, b, f)
__device__ int    g_cnt[NB];                // static zero-init; scan re-zeroes
__device__ int    g_off[NB + 1];
__device__ int    g_cur[NB];
__device__ int    g_csr[NE + 2];            // +2 pad: guard-free prefetch

// ---------------- fp16 quarter-row <-> fp32 helpers ------------------------
__device__ __forceinline__ float4 q_h2f(uint2 u) {
    float2 f0 = __half22float2(*reinterpret_cast<__half2*>(&u.x));
    float2 f1 = __half22float2(*reinterpret_cast<__half2*>(&u.y));
    return make_float4(f0.x, f0.y, f1.x, f1.y);
}
__device__ __forceinline__ uint2 q_f2h(float4 v) {
    __half2 h0 = __floats2half2_rn(v.x, v.y);
    __half2 h1 = __floats2half2_rn(v.z, v.w);
    uint2 u;
    u.x = *reinterpret_cast<unsigned*>(&h0);
    u.y = *reinterpret_cast<unsigned*>(&h1);
    return u;
}

// ---------------- CSR scan (re-zeroes counts for next graph replay) --------
__global__ void scan_kernel() {
    __shared__ int wsum[32];
    int t = threadIdx.x;
    int v[8];
    int s = 0;
#pragma unroll
    for (int i = 0; i < 8; i++) {
        v[i] = g_cnt[t * 8 + i];
        g_cnt[t * 8 + i] = 0;          // reset for next replay
        s += v[i];
    }
    unsigned lane = t & 31, wid = t >> 5;
    int x = s;
#pragma unroll
    for (int o = 1; o < 32; o <<= 1) {
        int y = __shfl_up_sync(0xffffffffu, x, o);
        if (lane >= (unsigned)o) x += y;
    }
    if (lane == 31) wsum[wid] = x;
    __syncthreads();
    if (wid == 0) {
        int w = wsum[lane];
#pragma unroll
        for (int o = 1; o < 32; o <<= 1) {
            int y = __shfl_up_sync(0xffffffffu, w, o);
            if (lane >= (unsigned)o) w += y;
        }
        wsum[lane] = w;
    }
    __syncthreads();
    int excl = x - s + (wid ? wsum[wid - 1] : 0);
    int run = excl;
#pragma unroll
    for (int i = 0; i < 8; i++) {
        g_off[t * 8 + i] = run;
        g_cur[t * 8 + i] = run;
        run += v[i];
    }
    if (t == 1023) g_off[NB] = run;
}

__global__ void fill_kernel(const int* __restrict__ neighbors) {
    int e = blockIdx.x * blockDim.x + threadIdx.x;
    if (e < NE) {
        int dst = neighbors[e];
        int pos = atomicAdd(&g_cur[dst], 1);
        g_csr[pos] = e / DD;   // source node of edge e
    }
}

// ---------------- layer-0 projections (quad-sliced, coalesced, fp16 out) ---
__global__ __launch_bounds__(256)
void proj0_kernel(const float* __restrict__ xin,
                  const float* __restrict__ neighbors_i,
                  const float* __restrict__ Wl, const float* __restrict__ Wr) {
    __shared__ float sWl[256], sWr[256];
    int t = threadIdx.x;
    sWl[t] = Wl[t];
    sWr[t] = Wr[t];

    // fused CSR count
    int e = blockIdx.x * 256 + t;
    if (e < NE) atomicAdd(&g_cnt[((const int*)neighbors_i)[e]], 1);
    __syncthreads();

    int row = blockIdx.x * 64 + (t >> 2);   // row = n*64 + b
    int hq  = t & 3;
    int n = row >> 6, b = row & 63;

    float4 xq = __ldcs((const float4*)(xin + ((size_t)b * NB + n) * HC) + hq);

    float4 ol  = make_float4(0.f, 0.f, 0.f, 0.f);
    float4 orr = ol;
    int qbase = (t & 31) & ~3;
#pragma unroll
    for (int f = 0; f < 16; f++) {
        float src = (f & 3) == 0 ? xq.x : (f & 3) == 1 ? xq.y
                  : (f & 3) == 2 ? xq.z : xq.w;
        float hf = __shfl_sync(0xffffffffu, src, qbase | (f >> 2), 32);
        float4 wl = *(const float4*)&sWl[f * 16 + hq * 4];
        float4 wr = *(const float4*)&sWr[f * 16 + hq * 4];
        ol.x  = fmaf(hf, wl.x, ol.x);  ol.y  = fmaf(hf, wl.y, ol.y);
        ol.z  = fmaf(hf, wl.z, ol.z);  ol.w  = fmaf(hf, wl.w, ol.w);
        orr.x = fmaf(hf, wr.x, orr.x); orr.y = fmaf(hf, wr.y, orr.y);
        orr.z = fmaf(hf, wr.z, orr.z); orr.w = fmaf(hf, wr.w, orr.w);
    }
    ((uint2*)(g_xlA + (size_t)row * HC))[hq] = q_f2h(ol);
    ((uint2*)(g_xrA + (size_t)row * HC))[hq] = q_f2h(orr);
}

// ---------------- fused GATv2 layer: 4 rows/thread, head-sliced, fp16 ------
// Block = 2 nodes, 128 threads = 2 x (16 quads). Thread (b0=(t&63)>>2,
// hq=t&3) handles batches b0, b0+16, b0+32, b0+48 of its node. Guard-free
// prefetch (g_csr padded). Forced 8 blocks/SM for occupancy.
template <int IN, bool LAST>
__global__ __launch_bounds__(128, 8)
void gat5_kernel(const float* __restrict__ attw,
                 const float* __restrict__ bias,
                 const float* __restrict__ Wln,   // next layer's Wl (null if LAST)
                 const float* __restrict__ Wrn) { // next layer's Wr (null if LAST)
    __shared__ float sWl[256], sWr[256];
    int t = threadIdx.x;

    const __half* __restrict__ xlin  = (IN == 0) ? g_xlA : g_xlB;
    const __half* __restrict__ xrin  = (IN == 0) ? g_xrA : g_xrB;
    __half*       __restrict__ xlout = (IN == 0) ? g_xlB : g_xlA;
    __half*       __restrict__ xrout = (IN == 0) ? g_xrB : g_xrA;

    int n  = blockIdx.x * 2 + (t >> 6);
    int t64 = t & 63;
    int b0 = t64 >> 2;         // 0..15
    int hq = t & 3;
    size_t base = (size_t)n * BB;
    int off0 = b0 * HC + hq * 4;           // half units; rows r at +16r*HC

    // ---- guard-free gather prefetches (csr padded by 2) -------------------
    int beg = __ldg(&g_off[n]), end = __ldg(&g_off[n + 1]);
    uint2 P0[4], P1[4];
    {
        const __half* p = xlin + (size_t)__ldg(&g_csr[beg]) * (BB * HC) + off0;
#pragma unroll
        for (int r = 0; r < 4; r++) P0[r] = *(const uint2*)(p + r * 16 * HC);
    }
    {
        const __half* p = xlin + (size_t)__ldg(&g_csr[beg + 1]) * (BB * HC) + off0;
#pragma unroll
        for (int r = 0; r < 4; r++) P1[r] = *(const uint2*)(p + r * 16 * HC);
    }

    // ---- stage next-layer weights (overlaps with prefetch latency) --------
    if (!LAST) {
        sWl[t] = Wln[t]; sWl[t + 128] = Wln[t + 128];
        sWr[t] = Wrn[t]; sWr[t + 128] = Wrn[t + 128];
    }

    const float LOG2E = 1.4426950408889634f;
    float4 att4 = __ldg((const float4*)attw + hq);
    att4.x *= LOG2E; att4.y *= LOG2E; att4.z *= LOG2E; att4.w *= LOG2E;

    float4 xr4[4];
#pragma unroll
    for (int r = 0; r < 4; r++)
        xr4[r] = q_h2f(*(const uint2*)(xrin + (base + b0 + 16 * r) * HC + hq * 4));

    // ---- self edges -------------------------------------------------------
    float s[4];
    float4 acc[4];
#pragma unroll
    for (int r = 0; r < 4; r++) {
        float4 v = q_h2f(*(const uint2*)(xlin + (base + b0 + 16 * r) * HC + hq * 4));
        float z, l;
        z = v.x + xr4[r].x; l  = fmaxf(z, 0.2f * z) * att4.x;
        z = v.y + xr4[r].y; l += fmaxf(z, 0.2f * z) * att4.y;
        z = v.z + xr4[r].z; l += fmaxf(z, 0.2f * z) * att4.z;
        z = v.w + xr4[r].w; l += fmaxf(z, 0.2f * z) * att4.w;
        float w = exp2f(l);
        s[r] = w;
        acc[r] = make_float4(w * v.x, w * v.y, w * v.z, w * v.w);
    }

    // ---- incoming-edge loop, 4 rows, 2-deep guard-free prefetch -----------
    for (int e = beg; e < end; e++) {
        float4 Q[4];
#pragma unroll
        for (int r = 0; r < 4; r++) { Q[r] = q_h2f(P0[r]); P0[r] = P1[r]; }
        {
            const __half* p = xlin + (size_t)__ldg(&g_csr[e + 2]) * (BB * HC) + off0;
#pragma unroll
            for (int r = 0; r < 4; r++) P1[r] = *(const uint2*)(p + r * 16 * HC);
        }
#pragma unroll
        for (int r = 0; r < 4; r++) {
            float z, l;
            z = Q[r].x + xr4[r].x; l  = fmaxf(z, 0.2f * z) * att4.x;
            z = Q[r].y + xr4[r].y; l += fmaxf(z, 0.2f * z) * att4.y;
            z = Q[r].z + xr4[r].z; l += fmaxf(z, 0.2f * z) * att4.z;
            z = Q[r].w + xr4[r].w; l += fmaxf(z, 0.2f * z) * att4.w;
            float w = exp2f(l);
            s[r] += w;
            acc[r].x = fmaf(w, Q[r].x, acc[r].x);
            acc[r].y = fmaf(w, Q[r].y, acc[r].y);
            acc[r].z = fmaf(w, Q[r].z, acc[r].z);
            acc[r].w = fmaf(w, Q[r].w, acc[r].w);
        }
    }

    // ---- finalize the 4 new h quarters -------------------------------------
    float4 bb4 = __ldg((const float4*)bias + hq);
    float4 o4[4];
#pragma unroll
    for (int r = 0; r < 4; r++) {
        float inv = 1.f / (s[r] + 1e-16f);
        o4[r] = make_float4(acc[r].x * inv + bb4.x, acc[r].y * inv + bb4.y,
                            acc[r].z * inv + bb4.z, acc[r].w * inv + bb4.w);
    }

    if (LAST) {
#pragma unroll
        for (int r = 0; r < 4; r++)
            *(uint2*)(g_h + (base + b0 + 16 * r) * HC + hq * 4) = q_f2h(o4[r]);
        return;
    }

    __syncthreads();                       // weights staged

    // ---- next-layer projections: quad shuffle, weights shared by 4 rows ---
    float4 ol[4], orr[4];
#pragma unroll
    for (int r = 0; r < 4; r++) {
        ol[r] = make_float4(0.f, 0.f, 0.f, 0.f);
        orr[r] = ol[r];
    }
    int qbase = (t & 31) & ~3;
#pragma unroll
    for (int f = 0; f < 16; f++) {
        float4 wl = *(const float4*)&sWl[f * 16 + hq * 4];
        float4 wr = *(const float4*)&sWr[f * 16 + hq * 4];
#pragma unroll
        for (int r = 0; r < 4; r++) {
            float src = (f & 3) == 0 ? o4[r].x : (f & 3) == 1 ? o4[r].y
                      : (f & 3) == 2 ? o4[r].z : o4[r].w;
            float hf = __shfl_sync(0xffffffffu, src, qbase | (f >> 2), 32);
            ol[r].x  = fmaf(hf, wl.x, ol[r].x);  ol[r].y  = fmaf(hf, wl.y, ol[r].y);
            ol[r].z  = fmaf(hf, wl.z, ol[r].z);  ol[r].w  = fmaf(hf, wl.w, ol[r].w);
            orr[r].x = fmaf(hf, wr.x, orr[r].x); orr[r].y = fmaf(hf, wr.y, orr[r].y);
            orr[r].z = fmaf(hf, wr.z, orr[r].z); orr[r].w = fmaf(hf, wr.w, orr[r].w);
        }
    }
#pragma unroll
    for (int r = 0; r < 4; r++) {
        size_t idx = base + b0 + 16 * r;
        *(uint2*)(xlout + idx * HC + hq * 4) = q_f2h(ol[r]);
        *(uint2*)(xrout + idx * HC + hq * 4) = q_f2h(orr[r]);
    }
}

// ---------------- mean-pool over nodes (phase 1: partial sums, fp16 h) -----
__global__ __launch_bounds__(256)
void pool1_kernel() {
    int b = blockIdx.x >> 3;       // 64 batches
    int chunk = blockIdx.x & 7;    // 8 node chunks of 1024
    int t = threadIdx.x;
    int f = t & 15, g = t >> 4;    // 16 groups
    float sum = 0.f;
    int n0 = chunk * 1024 + g;
    for (int k = 0; k < 64; k++) {
        int n = n0 + k * 16;
        sum += __half2float(g_h[((size_t)n * BB + b) * HC + f]);
    }
    __shared__ float red[256];
    red[t] = sum;
    __syncthreads();
    for (int st = 128; st >= 16; st >>= 1) {
        if (t < st) red[t] += red[t + st];
        __syncthreads();
    }
    if (t < 16) g_poolp[chunk * (BB * HC) + b * HC + t] = red[t];
}

// ---------------- agg MLP + edge scorer, one block per batch ---------------
__global__ __launch_bounds__(128)
void pool2_scorer_kernel(const int* __restrict__ agent_nodes,
                         const int* __restrict__ neighbors,
                         const float* __restrict__ Wg1, const float* __restrict__ bg1,
                         const float* __restrict__ Wg2, const float* __restrict__ bg2,
                         const float* __restrict__ We1, const float* __restrict__ be1,
                         const float* __restrict__ We2, const float* __restrict__ be2,
                         const float* __restrict__ We3, const float* __restrict__ be3,
                         float* __restrict__ out) {
    int b = blockIdx.x;
    int t = threadIdx.x;   // 128 threads
    __shared__ float pool[16], g1[32], agg[64];
    if (t < 16) {
        float s = 0.f;
#pragma unroll
        for (int c = 0; c < 8; c++) s += g_poolp[c * (BB * HC) + b * HC + t];
        pool[t] = s * (1.f / (float)NB);
    }
    __syncthreads();
    if (t < 32) {
        float s = bg1[t];
#pragma unroll
        for (int ff = 0; ff < 16; ff++) s = fmaf(pool[ff], Wg1[ff * 32 + t], s);
        g1[t] = tanhf(s);
    }
    __syncthreads();
    if (t < 64) {
        float s = bg2[t];
#pragma unroll
        for (int k = 0; k < 32; k++) s = fmaf(g1[k], Wg2[k * 64 + t], s);
        agg[t] = tanhf(s);
    }
    __syncthreads();

    if (t >= 3 * DD) return;          // 15 scorer items per batch
    int tk = t / DD;
    int d  = t % DD;
    int an = agent_nodes[b];
    int tg = neighbors[an * DD + d];

    float acc1[16];
#pragma unroll
    for (int o = 0; o < 16; o++) acc1[o] = be1[o];

#pragma unroll
    for (int ff = 0; ff < 16; ff++) {                       // source [0,16)
        float val = __half2float(g_h[((size_t)an * BB + b) * HC + ff]);
#pragma unroll
        for (int o = 0; o < 16; o++) acc1[o] = fmaf(val, We1[ff * 16 + o], acc1[o]);
    }
    {                                                       // token one-hot [16,19)
        int i = 16 + tk;
#pragma unroll
        for (int o = 0; o < 16; o++) acc1[o] += We1[i * 16 + o];
    }
#pragma unroll
    for (int ff = 0; ff < 16; ff++) {                       // target [19,35)
        float val = __half2float(g_h[((size_t)tg * BB + b) * HC + ff]);
#pragma unroll
        for (int o = 0; o < 16; o++) acc1[o] = fmaf(val, We1[(19 + ff) * 16 + o], acc1[o]);
    }
#pragma unroll
    for (int k = 0; k < 64; k++) {                          // agg [35,99)
        float val = agg[k];
#pragma unroll
        for (int o = 0; o < 16; o++) acc1[o] = fmaf(val, We1[(35 + k) * 16 + o], acc1[o]);
    }

    float e1[16];
#pragma unroll
    for (int o = 0; o < 16; o++) e1[o] = tanhf(acc1[o]);

    float e2[8];
#pragma unroll
    for (int o2 = 0; o2 < 8; o2++) {
        float s = be2[o2];
#pragma unroll
        for (int o = 0; o < 16; o++) s = fmaf(e1[o], We2[o * 8 + o2], s);
        e2[o2] = tanhf(s);
    }
    float s3 = be3[0];
#pragma unroll
    for (int o2 = 0; o2 < 8; o2++) s3 = fmaf(e2[o2], We3[o2], s3);
    out[b * (3 * DD) + t] = s3;
}

// ---------------- launch ---------------------------------------------------
extern "C" void kernel_launch(void* const* d_in, const int* in_sizes, int n_in,
                              void* d_out, int out_size) {
    const float* x      = (const float*)d_in[0];
    const int*   agent  = (const int*)  d_in[1];
    const int*   nbr    = (const int*)  d_in[2];
    const float* Wl     = (const float*)d_in[3];
    const float* Wr     = (const float*)d_in[4];
    const float* attw   = (const float*)d_in[5];
    const float* bias   = (const float*)d_in[6];
    const float* Wg1    = (const float*)d_in[7];
    const float* bg1    = (const float*)d_in[8];
    const float* Wg2    = (const float*)d_in[9];
    const float* bg2    = (const float*)d_in[10];
    const float* We1    = (const float*)d_in[11];
    const float* be1    = (const float*)d_in[12];
    const float* We2    = (const float*)d_in[13];
    const float* be2    = (const float*)d_in[14];
    const float* We3    = (const float*)d_in[15];
    const float* be3    = (const float*)d_in[16];
    float* out = (float*)d_out;

    // layer-0 projections (with fused CSR degree count)
    proj0_kernel<<<NT / 64, 256>>>(x, (const float*)nbr, Wl, Wr);
    scan_kernel<<<1, 1024>>>();
    fill_kernel<<<(NE + 255) / 256, 256>>>(nbr);

    // 4 fused GATv2 layers (buffers ping-pong A->B->A->B), 2 nodes/block,
    // 4 rows per thread
    gat5_kernel<0, false><<<NB / 2, 128>>>(attw,      bias,      Wl + 256, Wr + 256);
    gat5_kernel<1, false><<<NB / 2, 128>>>(attw + 16, bias + 16, Wl + 512, Wr + 512);
    gat5_kernel<0, false><<<NB / 2, 128>>>(attw + 32, bias + 32, Wl + 768, Wr + 768);
    gat5_kernel<1, true ><<<NB / 2, 128>>>(attw + 48, bias + 48, nullptr,  nullptr);

    // pooling partials, then agg-MLP + scorer fused (one block per batch)
    pool1_kernel<<<BB * 8, 256>>>();
    pool2_scorer_kernel<<<BB, 128>>>(agent, nbr, Wg1, bg1, Wg2, bg2,
                                     We1, be1, We2, be2, We3, be3, out);
}

// round 17
// speedup vs baseline: 1.0212x; 1.0212x over previous
#include <cuda_runtime.h>
#include <cuda_fp16.h>
#include <math.h>

#define NB 8192
#define BB 64
#define DD 5
#define NE (NB*DD)      // 40960 neighbor edges
#define NT (NB*BB)      // 524288 (node, batch) rows
#define HC 16

// ---------------- device scratch (no runtime allocation allowed) ------------
__device__ __half g_xlA[(size_t)NT * HC];   // 16.8 MB, layout (n,b,hc) fp16
__device__ __half g_xrA[(size_t)NT * HC];
__device__ __half g_xlB[(size_t)NT * HC];
__device__ __half g_xrB[(size_t)NT * HC];
__device__ __half g_h  [(size_t)NT * HC];   // final-layer h (fp16)
__device__ float  g_poolp[8 * BB * HC];     // pool partials (chunk, b, f)
__device__ int    g_cnt[NB];                // static zero-init; scan re-zeroes
__device__ int    g_off[NB + 1];
__device__ int    g_cur[NB];
__device__ int    g_csr[NE + 2];            // +2 pad: guard-free prefetch

// ---------------- fp16 quarter-row <-> fp32 helpers ------------------------
__device__ __forceinline__ float4 q_h2f(uint2 u) {
    float2 f0 = __half22float2(*reinterpret_cast<__half2*>(&u.x));
    float2 f1 = __half22float2(*reinterpret_cast<__half2*>(&u.y));
    return make_float4(f0.x, f0.y, f1.x, f1.y);
}
__device__ __forceinline__ uint2 q_f2h(float4 v) {
    __half2 h0 = __floats2half2_rn(v.x, v.y);
    __half2 h1 = __floats2half2_rn(v.z, v.w);
    uint2 u;
    u.x = *reinterpret_cast<unsigned*>(&h0);
    u.y = *reinterpret_cast<unsigned*>(&h1);
    return u;
}

// ---------------- CSR scan (re-zeroes counts for next graph replay) --------
__global__ void scan_kernel() {
    __shared__ int wsum[32];
    int t = threadIdx.x;
    int v[8];
    int s = 0;
#pragma unroll
    for (int i = 0; i < 8; i++) {
        v[i] = g_cnt[t * 8 + i];
        g_cnt[t * 8 + i] = 0;          // reset for next replay
        s += v[i];
    }
    unsigned lane = t & 31, wid = t >> 5;
    int x = s;
#pragma unroll
    for (int o = 1; o < 32; o <<= 1) {
        int y = __shfl_up_sync(0xffffffffu, x, o);
        if (lane >= (unsigned)o) x += y;
    }
    if (lane == 31) wsum[wid] = x;
    __syncthreads();
    if (wid == 0) {
        int w = wsum[lane];
#pragma unroll
        for (int o = 1; o < 32; o <<= 1) {
            int y = __shfl_up_sync(0xffffffffu, w, o);
            if (lane >= (unsigned)o) w += y;
        }
        wsum[lane] = w;
    }
    __syncthreads();
    int excl = x - s + (wid ? wsum[wid - 1] : 0);
    int run = excl;
#pragma unroll
    for (int i = 0; i < 8; i++) {
        g_off[t * 8 + i] = run;
        g_cur[t * 8 + i] = run;
        run += v[i];
    }
    if (t == 1023) g_off[NB] = run;
}

__global__ void fill_kernel(const int* __restrict__ neighbors) {
    int e = blockIdx.x * blockDim.x + threadIdx.x;
    if (e < NE) {
        int dst = neighbors[e];
        int pos = atomicAdd(&g_cur[dst], 1);
        g_csr[pos] = e / DD;   // source node of edge e
    }
}

// ---------------- layer-0 projections (quad-sliced, coalesced, fp16 out) ---
__global__ __launch_bounds__(256)
void proj0_kernel(const float* __restrict__ xin,
                  const float* __restrict__ neighbors_i,
                  const float* __restrict__ Wl, const float* __restrict__ Wr) {
    __shared__ float sWl[256], sWr[256];
    int t = threadIdx.x;
    sWl[t] = Wl[t];
    sWr[t] = Wr[t];

    // fused CSR count
    int e = blockIdx.x * 256 + t;
    if (e < NE) atomicAdd(&g_cnt[((const int*)neighbors_i)[e]], 1);
    __syncthreads();

    int row = blockIdx.x * 64 + (t >> 2);   // row = n*64 + b
    int hq  = t & 3;
    int n = row >> 6, b = row & 63;

    float4 xq = __ldcs((const float4*)(xin + ((size_t)b * NB + n) * HC) + hq);

    float4 ol  = make_float4(0.f, 0.f, 0.f, 0.f);
    float4 orr = ol;
    int qbase = (t & 31) & ~3;
#pragma unroll
    for (int f = 0; f < 16; f++) {
        float src = (f & 3) == 0 ? xq.x : (f & 3) == 1 ? xq.y
                  : (f & 3) == 2 ? xq.z : xq.w;
        float hf = __shfl_sync(0xffffffffu, src, qbase | (f >> 2), 32);
        float4 wl = *(const float4*)&sWl[f * 16 + hq * 4];
        float4 wr = *(const float4*)&sWr[f * 16 + hq * 4];
        ol.x  = fmaf(hf, wl.x, ol.x);  ol.y  = fmaf(hf, wl.y, ol.y);
        ol.z  = fmaf(hf, wl.z, ol.z);  ol.w  = fmaf(hf, wl.w, ol.w);
        orr.x = fmaf(hf, wr.x, orr.x); orr.y = fmaf(hf, wr.y, orr.y);
        orr.z = fmaf(hf, wr.z, orr.z); orr.w = fmaf(hf, wr.w, orr.w);
    }
    ((uint2*)(g_xlA + (size_t)row * HC))[hq] = q_f2h(ol);
    ((uint2*)(g_xrA + (size_t)row * HC))[hq] = q_f2h(orr);
}

// ---------------- fused GATv2 layer: 4 rows/thread, head-sliced, fp16 ------
// Block = 2 nodes, 128 threads = 2 x (16 quads). Thread (b0=(t&63)>>2,
// hq=t&3) handles batches b0, b0+16, b0+32, b0+48 of its node. Guard-free
// prefetch (g_csr padded). Natural register allocation (no occupancy cap).
template <int IN, bool LAST>
__global__ __launch_bounds__(128)
void gat5_kernel(const float* __restrict__ attw,
                 const float* __restrict__ bias,
                 const float* __restrict__ Wln,   // next layer's Wl (null if LAST)
                 const float* __restrict__ Wrn) { // next layer's Wr (null if LAST)
    __shared__ float sWl[256], sWr[256];
    int t = threadIdx.x;

    const __half* __restrict__ xlin  = (IN == 0) ? g_xlA : g_xlB;
    const __half* __restrict__ xrin  = (IN == 0) ? g_xrA : g_xrB;
    __half*       __restrict__ xlout = (IN == 0) ? g_xlB : g_xlA;
    __half*       __restrict__ xrout = (IN == 0) ? g_xrB : g_xrA;

    int n  = blockIdx.x * 2 + (t >> 6);
    int t64 = t & 63;
    int b0 = t64 >> 2;         // 0..15
    int hq = t & 3;
    size_t base = (size_t)n * BB;
    int off0 = b0 * HC + hq * 4;           // half units; rows r at +16r*HC

    // ---- guard-free gather prefetches (csr padded by 2) -------------------
    int beg = __ldg(&g_off[n]), end = __ldg(&g_off[n + 1]);
    uint2 P0[4], P1[4];
    {
        const __half* p = xlin + (size_t)__ldg(&g_csr[beg]) * (BB * HC) + off0;
#pragma unroll
        for (int r = 0; r < 4; r++) P0[r] = *(const uint2*)(p + r * 16 * HC);
    }
    {
        const __half* p = xlin + (size_t)__ldg(&g_csr[beg + 1]) * (BB * HC) + off0;
#pragma unroll
        for (int r = 0; r < 4; r++) P1[r] = *(const uint2*)(p + r * 16 * HC);
    }

    // ---- stage next-layer weights (overlaps with prefetch latency) --------
    if (!LAST) {
        sWl[t] = Wln[t]; sWl[t + 128] = Wln[t + 128];
        sWr[t] = Wrn[t]; sWr[t + 128] = Wrn[t + 128];
    }

    const float LOG2E = 1.4426950408889634f;
    float4 att4 = __ldg((const float4*)attw + hq);
    att4.x *= LOG2E; att4.y *= LOG2E; att4.z *= LOG2E; att4.w *= LOG2E;

    float4 xr4[4];
#pragma unroll
    for (int r = 0; r < 4; r++)
        xr4[r] = q_h2f(*(const uint2*)(xrin + (base + b0 + 16 * r) * HC + hq * 4));

    // ---- self edges -------------------------------------------------------
    float s[4];
    float4 acc[4];
#pragma unroll
    for (int r = 0; r < 4; r++) {
        float4 v = q_h2f(*(const uint2*)(xlin + (base + b0 + 16 * r) * HC + hq * 4));
        float z, l;
        z = v.x + xr4[r].x; l  = fmaxf(z, 0.2f * z) * att4.x;
        z = v.y + xr4[r].y; l += fmaxf(z, 0.2f * z) * att4.y;
        z = v.z + xr4[r].z; l += fmaxf(z, 0.2f * z) * att4.z;
        z = v.w + xr4[r].w; l += fmaxf(z, 0.2f * z) * att4.w;
        float w = exp2f(l);
        s[r] = w;
        acc[r] = make_float4(w * v.x, w * v.y, w * v.z, w * v.w);
    }

    // ---- incoming-edge loop, 4 rows, 2-deep guard-free prefetch -----------
    for (int e = beg; e < end; e++) {
        float4 Q[4];
#pragma unroll
        for (int r = 0; r < 4; r++) { Q[r] = q_h2f(P0[r]); P0[r] = P1[r]; }
        {
            const __half* p = xlin + (size_t)__ldg(&g_csr[e + 2]) * (BB * HC) + off0;
#pragma unroll
            for (int r = 0; r < 4; r++) P1[r] = *(const uint2*)(p + r * 16 * HC);
        }
#pragma unroll
        for (int r = 0; r < 4; r++) {
            float z, l;
            z = Q[r].x + xr4[r].x; l  = fmaxf(z, 0.2f * z) * att4.x;
            z = Q[r].y + xr4[r].y; l += fmaxf(z, 0.2f * z) * att4.y;
            z = Q[r].z + xr4[r].z; l += fmaxf(z, 0.2f * z) * att4.z;
            z = Q[r].w + xr4[r].w; l += fmaxf(z, 0.2f * z) * att4.w;
            float w = exp2f(l);
            s[r] += w;
            acc[r].x = fmaf(w, Q[r].x, acc[r].x);
            acc[r].y = fmaf(w, Q[r].y, acc[r].y);
            acc[r].z = fmaf(w, Q[r].z, acc[r].z);
            acc[r].w = fmaf(w, Q[r].w, acc[r].w);
        }
    }

    // ---- finalize the 4 new h quarters -------------------------------------
    float4 bb4 = __ldg((const float4*)bias + hq);
    float4 o4[4];
#pragma unroll
    for (int r = 0; r < 4; r++) {
        float inv = 1.f / (s[r] + 1e-16f);
        o4[r] = make_float4(acc[r].x * inv + bb4.x, acc[r].y * inv + bb4.y,
                            acc[r].z * inv + bb4.z, acc[r].w * inv + bb4.w);
    }

    if (LAST) {
#pragma unroll
        for (int r = 0; r < 4; r++)
            *(uint2*)(g_h + (base + b0 + 16 * r) * HC + hq * 4) = q_f2h(o4[r]);
        return;
    }

    __syncthreads();                       // weights staged

    // ---- next-layer projections: quad shuffle, weights shared by 4 rows ---
    float4 ol[4], orr[4];
#pragma unroll
    for (int r = 0; r < 4; r++) {
        ol[r] = make_float4(0.f, 0.f, 0.f, 0.f);
        orr[r] = ol[r];
    }
    int qbase = (t & 31) & ~3;
#pragma unroll
    for (int f = 0; f < 16; f++) {
        float4 wl = *(const float4*)&sWl[f * 16 + hq * 4];
        float4 wr = *(const float4*)&sWr[f * 16 + hq * 4];
#pragma unroll
        for (int r = 0; r < 4; r++) {
            float src = (f & 3) == 0 ? o4[r].x : (f & 3) == 1 ? o4[r].y
                      : (f & 3) == 2 ? o4[r].z : o4[r].w;
            float hf = __shfl_sync(0xffffffffu, src, qbase | (f >> 2), 32);
            ol[r].x  = fmaf(hf, wl.x, ol[r].x);  ol[r].y  = fmaf(hf, wl.y, ol[r].y);
            ol[r].z  = fmaf(hf, wl.z, ol[r].z);  ol[r].w  = fmaf(hf, wl.w, ol[r].w);
            orr[r].x = fmaf(hf, wr.x, orr[r].x); orr[r].y = fmaf(hf, wr.y, orr[r].y);
            orr[r].z = fmaf(hf, wr.z, orr[r].z); orr[r].w = fmaf(hf, wr.w, orr[r].w);
        }
    }
#pragma unroll
    for (int r = 0; r < 4; r++) {
        size_t idx = base + b0 + 16 * r;
        *(uint2*)(xlout + idx * HC + hq * 4) = q_f2h(ol[r]);
        *(uint2*)(xrout + idx * HC + hq * 4) = q_f2h(orr[r]);
    }
}

// ---------------- mean-pool over nodes (phase 1: partial sums, fp16 h) -----
__global__ __launch_bounds__(256)
void pool1_kernel() {
    int b = blockIdx.x >> 3;       // 64 batches
    int chunk = blockIdx.x & 7;    // 8 node chunks of 1024
    int t = threadIdx.x;
    int f = t & 15, g = t >> 4;    // 16 groups
    float sum = 0.f;
    int n0 = chunk * 1024 + g;
    for (int k = 0; k < 64; k++) {
        int n = n0 + k * 16;
        sum += __half2float(g_h[((size_t)n * BB + b) * HC + f]);
    }
    __shared__ float red[256];
    red[t] = sum;
    __syncthreads();
    for (int st = 128; st >= 16; st >>= 1) {
        if (t < st) red[t] += red[t + st];
        __syncthreads();
    }
    if (t < 16) g_poolp[chunk * (BB * HC) + b * HC + t] = red[t];
}

// ---------------- agg MLP + edge scorer, one block per batch ---------------
__global__ __launch_bounds__(128)
void pool2_scorer_kernel(const int* __restrict__ agent_nodes,
                         const int* __restrict__ neighbors,
                         const float* __restrict__ Wg1, const float* __restrict__ bg1,
                         const float* __restrict__ Wg2, const float* __restrict__ bg2,
                         const float* __restrict__ We1, const float* __restrict__ be1,
                         const float* __restrict__ We2, const float* __restrict__ be2,
                         const float* __restrict__ We3, const float* __restrict__ be3,
                         float* __restrict__ out) {
    int b = blockIdx.x;
    int t = threadIdx.x;   // 128 threads
    __shared__ float pool[16], g1[32], agg[64];
    if (t < 16) {
        float s = 0.f;
#pragma unroll
        for (int c = 0; c < 8; c++) s += g_poolp[c * (BB * HC) + b * HC + t];
        pool[t] = s * (1.f / (float)NB);
    }
    __syncthreads();
    if (t < 32) {
        float s = bg1[t];
#pragma unroll
        for (int ff = 0; ff < 16; ff++) s = fmaf(pool[ff], Wg1[ff * 32 + t], s);
        g1[t] = tanhf(s);
    }
    __syncthreads();
    if (t < 64) {
        float s = bg2[t];
#pragma unroll
        for (int k = 0; k < 32; k++) s = fmaf(g1[k], Wg2[k * 64 + t], s);
        agg[t] = tanhf(s);
    }
    __syncthreads();

    if (t >= 3 * DD) return;          // 15 scorer items per batch
    int tk = t / DD;
    int d  = t % DD;
    int an = agent_nodes[b];
    int tg = neighbors[an * DD + d];

    float acc1[16];
#pragma unroll
    for (int o = 0; o < 16; o++) acc1[o] = be1[o];

#pragma unroll
    for (int ff = 0; ff < 16; ff++) {                       // source [0,16)
        float val = __half2float(g_h[((size_t)an * BB + b) * HC + ff]);
#pragma unroll
        for (int o = 0; o < 16; o++) acc1[o] = fmaf(val, We1[ff * 16 + o], acc1[o]);
    }
    {                                                       // token one-hot [16,19)
        int i = 16 + tk;
#pragma unroll
        for (int o = 0; o < 16; o++) acc1[o] += We1[i * 16 + o];
    }
#pragma unroll
    for (int ff = 0; ff < 16; ff++) {                       // target [19,35)
        float val = __half2float(g_h[((size_t)tg * BB + b) * HC + ff]);
#pragma unroll
        for (int o = 0; o < 16; o++) acc1[o] = fmaf(val, We1[(19 + ff) * 16 + o], acc1[o]);
    }
#pragma unroll
    for (int k = 0; k < 64; k++) {                          // agg [35,99)
        float val = agg[k];
#pragma unroll
        for (int o = 0; o < 16; o++) acc1[o] = fmaf(val, We1[(35 + k) * 16 + o], acc1[o]);
    }

    float e1[16];
#pragma unroll
    for (int o = 0; o < 16; o++) e1[o] = tanhf(acc1[o]);

    float e2[8];
#pragma unroll
    for (int o2 = 0; o2 < 8; o2++) {
        float s = be2[o2];
#pragma unroll
        for (int o = 0; o < 16; o++) s = fmaf(e1[o], We2[o * 8 + o2], s);
        e2[o2] = tanhf(s);
    }
    float s3 = be3[0];
#pragma unroll
    for (int o2 = 0; o2 < 8; o2++) s3 = fmaf(e2[o2], We3[o2], s3);
    out[b * (3 * DD) + t] = s3;
}

// ---------------- launch ---------------------------------------------------
extern "C" void kernel_launch(void* const* d_in, const int* in_sizes, int n_in,
                              void* d_out, int out_size) {
    const float* x      = (const float*)d_in[0];
    const int*   agent  = (const int*)  d_in[1];
    const int*   nbr    = (const int*)  d_in[2];
    const float* Wl     = (const float*)d_in[3];
    const float* Wr     = (const float*)d_in[4];
    const float* attw   = (const float*)d_in[5];
    const float* bias   = (const float*)d_in[6];
    const float* Wg1    = (const float*)d_in[7];
    const float* bg1    = (const float*)d_in[8];
    const float* Wg2    = (const float*)d_in[9];
    const float* bg2    = (const float*)d_in[10];
    const float* We1    = (const float*)d_in[11];
    const float* be1    = (const float*)d_in[12];
    const float* We2    = (const float*)d_in[13];
    const float* be2    = (const float*)d_in[14];
    const float* We3    = (const float*)d_in[15];
    const float* be3    = (const float*)d_in[16];
    float* out = (float*)d_out;

    // layer-0 projections (with fused CSR degree count)
    proj0_kernel<<<NT / 64, 256>>>(x, (const float*)nbr, Wl, Wr);
    scan_kernel<<<1, 1024>>>();
    fill_kernel<<<(NE + 255) / 256, 256>>>(nbr);

    // 4 fused GATv2 layers (buffers ping-pong A->B->A->B), 2 nodes/block,
    // 4 rows per thread
    gat5_kernel<0, false><<<NB / 2, 128>>>(attw,      bias,      Wl + 256, Wr + 256);
    gat5_kernel<1, false><<<NB / 2, 128>>>(attw + 16, bias + 16, Wl + 512, Wr + 512);
    gat5_kernel<0, false><<<NB / 2, 128>>>(attw + 32, bias + 32, Wl + 768, Wr + 768);
    gat5_kernel<1, true ><<<NB / 2, 128>>>(attw + 48, bias + 48, nullptr,  nullptr);

    // pooling partials, then agg-MLP + scorer fused (one block per batch)
    pool1_kernel<<<BB * 8, 256>>>();
    pool2_scorer_kernel<<<BB, 128>>>(agent, nbr, Wg1, bg1, Wg2, bg2,
                                     We1, be1, We2, be2, We3, be3, out);
}